// round 1
// baseline (speedup 1.0000x reference)
#include <cuda_runtime.h>
#include <cstddef>

// Problem constants
#define NB   4096
#define NN   29
#define NC   6
#define CDIM 16
#define DD   22      // NC + CDIM
#define HDIM 64
#define NL   2
#define NOUT 24      // (IDX1-IDX0)*NC*2
#define OUTROW 12    // NC*2
#define ZROW 25      // padded row stride for z / zn (gcd(25,32)=1 -> conflict-free)

// Shared memory layout (float offsets). All float4-aligned where needed.
#define OFF_Z     0        // 32*25 = 800
#define OFF_ZN    800      // 800
#define OFF_PIT   1600     // 64*32 = 2048
#define OFF_PJT   3648     // 2048
#define OFF_W2    5696     // 64*64 = 4096
#define OFF_EW1   9792     // 44*64 = 2816
#define OFF_M1T   12608    // 64*128 = 8192
#define OFF_MAGG  20800    // 2*32*64 = 4096
#define SMEM_FLOATS 24896  // 99584 bytes

__device__ __forceinline__ float siluf(float v) {
    return v / (1.0f + __expf(-v));
}
__device__ __forceinline__ float sigm(float v) {
    return 1.0f / (1.0f + __expf(-v));
}

extern "C" __global__ void __launch_bounds__(256, 2)
gnn_kernel(const float* __restrict__ x,   const float* __restrict__ ctx,
           const float* __restrict__ eW1, const float* __restrict__ eb1,
           const float* __restrict__ eW2, const float* __restrict__ eb2,
           const float* __restrict__ gW,  const float* __restrict__ gb,
           const float* __restrict__ lng, const float* __restrict__ lnb,
           const float* __restrict__ nW1, const float* __restrict__ nb1,
           const float* __restrict__ nW2, const float* __restrict__ nb2,
           const float* __restrict__ hW1, const float* __restrict__ hb1,
           const float* __restrict__ hW2, const float* __restrict__ hb2,
           float* __restrict__ out)
{
    extern __shared__ float sh[];
    float* zsh   = sh + OFF_Z;     // [32][25] node features (residual stream)
    float* znsh  = sh + OFF_ZN;    // [32][25] layernormed features
    float* piT   = sh + OFF_PIT;   // [64][32] source projection (k-major), bias folded
    float* pjT   = sh + OFF_PJT;   // [64][32] target projection (k-major)
    float* w2sh  = sh + OFF_W2;    // [64][64] eW2 (k-major rows = contraction dim)
    float* ew1sh = sh + OFF_EW1;   // [44][64]
    float* m1T   = sh + OFF_M1T;   // [64][128] m1 tile, k-major; reused as h[29][64]
    float* magg  = sh + OFF_MAGG;  // [2][32][64] parity-split edge aggregate

    const int b = blockIdx.x;
    const int t = threadIdx.x;

    // ---- load z = concat(x, context) ----
    for (int idx = t; idx < NN * DD; idx += 256) {
        int i = idx / DD, d = idx - i * DD;
        float v = (d < NC) ? x[(b * NN + i) * NC + d]
                           : ctx[(b * NN + i) * CDIM + (d - NC)];
        zsh[i * ZROW + d] = v;
    }
    __syncthreads();

    // ---- GEMM thread geometry (fixed for all tiles) ----
    const int w    = t >> 5;
    const int lane = t & 31;
    const int lr   = lane >> 4;        // 0..1 (row-half within warp)
    const int lc   = lane & 15;        // 0..15 (column group)
    const int iiW  = w >> 1;           // 0..3: which i within the i-group
    const int par  = w & 1;            // jj half parity
    const int rtbase  = iiW * 32 + par * 16 + lr * 8;   // 8 tile rows
    const int jjbase  = par * 16 + lr * 8;               // jj of row 0
    const int colbase = lc * 4;

    for (int l = 0; l < NL; ++l) {
        const float* eW1l = eW1 + l * 2 * DD * HDIM;
        const float* eb1l = eb1 + l * HDIM;
        const float* eW2l = eW2 + l * HDIM * HDIM;
        const float* eb2l = eb2 + l * HDIM;
        const float* gWl  = gW  + l * HDIM;
        const float  gbl  = gb[l];
        const float* lngl = lng + l * DD;
        const float* lnbl = lnb + l * DD;
        const float* nW1l = nW1 + l * (DD + HDIM) * HDIM;
        const float* nb1l = nb1 + l * HDIM;
        const float* nW2l = nW2 + l * HDIM * DD;
        const float* nb2l = nb2 + l * DD;

        // ---- stage weights ----
        for (int idx = t; idx < HDIM * HDIM; idx += 256) w2sh[idx]  = eW2l[idx];
        for (int idx = t; idx < 2 * DD * HDIM; idx += 256) ew1sh[idx] = eW1l[idx];
        __syncthreads();

        // ---- pi / pj projections (transposed, eb1 folded into pi) ----
        for (int idx = t; idx < HDIM * 32; idx += 256) {
            int k = idx >> 5, i = idx & 31;
            float aI = 0.f, aJ = 0.f;
            if (i < NN) {
                #pragma unroll
                for (int d = 0; d < DD; ++d) {
                    float zv = zsh[i * ZROW + d];
                    aI += zv * ew1sh[d * HDIM + k];
                    aJ += zv * ew1sh[(DD + d) * HDIM + k];
                }
                aI += eb1l[k];
            }
            piT[k * 32 + i] = aI;
            pjT[k * 32 + i] = aJ;
        }
        __syncthreads();

        // per-thread epilogue constants
        float eb2v[4], gwv[4];
        #pragma unroll
        for (int c = 0; c < 4; ++c) {
            eb2v[c] = eb2l[colbase + c];
            gwv[c]  = gWl[colbase + c];
        }

        // ---- 8 pair tiles: (4 i's) x (32 padded j's) = 128 rows x 64 cols ----
        for (int ig = 0; ig < 8; ++ig) {
            // fill m1T[k][rt] = silu(pi[i][k] + pj[jj][k])
            for (int e = t; e < HDIM * 128; e += 256) {
                int k = e >> 7, rt = e & 127;
                float s = piT[k * 32 + ig * 4 + (rt >> 5)] + pjT[k * 32 + (rt & 31)];
                m1T[e] = siluf(s);
            }
            __syncthreads();

            // 8x4 register-tile GEMM: acc = m1 @ eW2
            float acc[8][4];
            #pragma unroll
            for (int r = 0; r < 8; ++r)
                #pragma unroll
                for (int c = 0; c < 4; ++c) acc[r][c] = 0.f;

            const float* aB = m1T + rtbase;
            const float* bB = w2sh + colbase;
            #pragma unroll 8
            for (int k = 0; k < HDIM; ++k) {
                float4 a0 = *(const float4*)(aB + k * 128);
                float4 a1 = *(const float4*)(aB + k * 128 + 4);
                float4 bv = *(const float4*)(bB + k * HDIM);
                float av[8] = {a0.x, a0.y, a0.z, a0.w, a1.x, a1.y, a1.z, a1.w};
                float bl2[4] = {bv.x, bv.y, bv.z, bv.w};
                #pragma unroll
                for (int r = 0; r < 8; ++r)
                    #pragma unroll
                    for (int c = 0; c < 4; ++c)
                        acc[r][c] += av[r] * bl2[c];
            }

            // epilogue: silu, gate, masked aggregate over j
            float g_r[8];
            #pragma unroll
            for (int r = 0; r < 8; ++r) {
                float gp = 0.f;
                #pragma unroll
                for (int c = 0; c < 4; ++c) {
                    float v = siluf(acc[r][c] + eb2v[c]);
                    acc[r][c] = v;
                    gp += v * gwv[c];
                }
                gp += __shfl_xor_sync(0xffffffffu, gp, 1);
                gp += __shfl_xor_sync(0xffffffffu, gp, 2);
                gp += __shfl_xor_sync(0xffffffffu, gp, 4);
                gp += __shfl_xor_sync(0xffffffffu, gp, 8);
                g_r[r] = sigm(gp + gbl);
            }
            float s4[4] = {0.f, 0.f, 0.f, 0.f};
            #pragma unroll
            for (int r = 0; r < 8; ++r) {
                if (jjbase + r < NN) {
                    #pragma unroll
                    for (int c = 0; c < 4; ++c) s4[c] += acc[r][c] * g_r[r];
                }
            }
            #pragma unroll
            for (int c = 0; c < 4; ++c)
                s4[c] += __shfl_xor_sync(0xffffffffu, s4[c], 16);
            int iNode = ig * 4 + iiW;
            if (lr == 0 && iNode < NN) {
                #pragma unroll
                for (int c = 0; c < 4; ++c)
                    magg[par * 2048 + iNode * HDIM + colbase + c] = s4[c];
            }
            __syncthreads();
        }

        // combine parity halves of the aggregate
        for (int idx = t; idx < NN * HDIM; idx += 256)
            magg[idx] += magg[2048 + idx];

        // layernorm (norm_feats)
        if (t < NN) {
            float mu = 0.f, sq = 0.f;
            #pragma unroll
            for (int d = 0; d < DD; ++d) {
                float v = zsh[t * ZROW + d];
                mu += v; sq += v * v;
            }
            mu *= (1.0f / DD);
            float var = sq * (1.0f / DD) - mu * mu;
            float rs = rsqrtf(var + 1e-5f);
            #pragma unroll
            for (int d = 0; d < DD; ++d)
                znsh[t * ZROW + d] = (zsh[t * ZROW + d] - mu) * rs * lngl[d] + lnbl[d];
        }
        __syncthreads();

        // node MLP layer 1: h = silu(concat(zn, m_i) @ nW1 + nb1)  (h stored in m1T)
        for (int idx = t; idx < NN * HDIM; idx += 256) {
            int i = idx >> 6, m = idx & 63;
            float a = nb1l[m];
            #pragma unroll
            for (int d = 0; d < DD; ++d)
                a += znsh[i * ZROW + d] * nW1l[d * HDIM + m];
            const float* mg = magg + i * HDIM;
            #pragma unroll 8
            for (int d2 = 0; d2 < HDIM; ++d2)
                a += mg[d2] * nW1l[(DD + d2) * HDIM + m];
            m1T[idx] = siluf(a);
        }
        __syncthreads();

        // node MLP layer 2 + residual
        for (int idx = t; idx < NN * DD; idx += 256) {
            int i = idx / DD, d = idx - i * DD;
            float a = nb2l[d];
            #pragma unroll 8
            for (int m2 = 0; m2 < HDIM; ++m2)
                a += m1T[i * HDIM + m2] * nW2l[m2 * DD + d];
            zsh[i * ZROW + d] += a;
        }
        __syncthreads();
    }

    // ---- mean pool over nodes ----
    if (t < DD) {
        float s = 0.f;
        #pragma unroll
        for (int i = 0; i < NN; ++i) s += zsh[i * ZROW + t];
        znsh[t] = s * (1.0f / NN);
    }
    __syncthreads();

    // ---- head MLP ----
    if (t < HDIM) {
        float a = hb1[t];
        #pragma unroll
        for (int d = 0; d < DD; ++d) a += znsh[d] * hW1[d * HDIM + t];
        piT[t] = fmaxf(a, 0.f);
    }
    __syncthreads();

    float* ob = out + (size_t)b * (NN * OUTROW);
    for (int idx = t; idx < NN * OUTROW; idx += 256) {
        float v = 0.f;
        if (idx < NOUT) {
            v = hb2[idx];
            #pragma unroll
            for (int m2 = 0; m2 < HDIM; ++m2)
                v += piT[m2] * hW2[m2 * NOUT + idx];
        }
        ob[idx] = v;
    }
}

extern "C" void kernel_launch(void* const* d_in, const int* in_sizes, int n_in,
                              void* d_out, int out_size) {
    (void)in_sizes; (void)n_in; (void)out_size;
    const float* x    = (const float*)d_in[0];
    const float* ctx  = (const float*)d_in[1];
    const float* eW1  = (const float*)d_in[2];
    const float* eb1  = (const float*)d_in[3];
    const float* eW2  = (const float*)d_in[4];
    const float* eb2  = (const float*)d_in[5];
    const float* gW   = (const float*)d_in[6];
    const float* gb   = (const float*)d_in[7];
    const float* lng  = (const float*)d_in[8];
    const float* lnb  = (const float*)d_in[9];
    const float* nW1  = (const float*)d_in[10];
    const float* nb1  = (const float*)d_in[11];
    const float* nW2  = (const float*)d_in[12];
    const float* nb2  = (const float*)d_in[13];
    const float* hW1  = (const float*)d_in[14];
    const float* hb1  = (const float*)d_in[15];
    const float* hW2  = (const float*)d_in[16];
    const float* hb2  = (const float*)d_in[17];
    float* out = (float*)d_out;

    cudaFuncSetAttribute(gnn_kernel, cudaFuncAttributeMaxDynamicSharedMemorySize,
                         SMEM_FLOATS * sizeof(float));
    gnn_kernel<<<NB, 256, SMEM_FLOATS * sizeof(float)>>>(
        x, ctx, eW1, eb1, eW2, eb2, gW, gb, lng, lnb,
        nW1, nb1, nW2, nb2, hW1, hb1, hW2, hb2, out);
}

// round 2
// speedup vs baseline: 2.2783x; 2.2783x over previous
#include <cuda_runtime.h>
#include <cstdint>
#include <cstddef>

// Problem constants
#define NB   4096
#define NN   29
#define NC   6
#define CDIM 16
#define DD   22
#define HDIM 64
#define NL   2
#define NOUT 24
#define OUTROW 12
#define ZROW 25     // pad for z/zn rows
#define PROW 76     // pad for pi/pj rows (conflict-free frag loads)
#define WROW 72     // pad for W2 rows (conflict-free B frag loads)

// Shared memory layout (float offsets)
#define OFF_Z    0        // 32*25  = 800
#define OFF_ZN   800      // 800
#define OFF_PI   1600     // 32*76  = 2432
#define OFF_PJ   4032     // 2432
#define OFF_W2   6464     // 64*72  = 4608  (tf32-rounded)
#define OFF_EW1  11072    // 44*64  = 2816
#define OFF_GB   13888    // 2*2*4*32 = 512 (gate exchange, double-buffered)
#define OFF_MAGG 14400    // 32*64  = 2048
#define OFF_H    16448    // 32*64  = 2048
#define SMEM_FLOATS 18496 // 73984 bytes

__device__ __forceinline__ float siluf(float v) {
    float e = __expf(-v);
    return v * __fdividef(1.0f, 1.0f + e);
}
__device__ __forceinline__ float sigm(float v) {
    float e = __expf(-v);
    return __fdividef(1.0f, 1.0f + e);
}
__device__ __forceinline__ uint32_t tf32_rna(float x) {
    uint32_t u;
    asm("cvt.rna.tf32.f32 %0, %1;" : "=r"(u) : "f"(x));
    return u;
}
__device__ __forceinline__ void mma_tf32(float c[4], const uint32_t a[4],
                                         uint32_t b0, uint32_t b1) {
    asm volatile(
        "mma.sync.aligned.m16n8k8.row.col.f32.tf32.tf32.f32 "
        "{%0,%1,%2,%3}, {%4,%5,%6,%7}, {%8,%9}, {%0,%1,%2,%3};\n"
        : "+f"(c[0]), "+f"(c[1]), "+f"(c[2]), "+f"(c[3])
        : "r"(a[0]), "r"(a[1]), "r"(a[2]), "r"(a[3]), "r"(b0), "r"(b1));
}

extern "C" __global__ void __launch_bounds__(256, 2)
gnn_kernel(const float* __restrict__ x,   const float* __restrict__ ctx,
           const float* __restrict__ eW1, const float* __restrict__ eb1,
           const float* __restrict__ eW2, const float* __restrict__ eb2,
           const float* __restrict__ gW,  const float* __restrict__ gb,
           const float* __restrict__ lng, const float* __restrict__ lnb,
           const float* __restrict__ nW1, const float* __restrict__ nb1,
           const float* __restrict__ nW2, const float* __restrict__ nb2,
           const float* __restrict__ hW1, const float* __restrict__ hb1,
           const float* __restrict__ hW2, const float* __restrict__ hb2,
           float* __restrict__ out)
{
    extern __shared__ float sh[];
    float* zsh   = sh + OFF_Z;
    float* znsh  = sh + OFF_ZN;
    float* piR   = sh + OFF_PI;    // [32][76] row-major, eb1 folded
    float* pjR   = sh + OFF_PJ;    // [32][76]
    float* w2sh  = sh + OFF_W2;    // [64][72] tf32-rounded
    float* ew1sh = sh + OFF_EW1;   // [44][64]
    float* gbuf  = sh + OFF_GB;    // [parity][nh][i_sel][32]
    float* magg  = sh + OFF_MAGG;  // [32][64]
    float* hbuf  = sh + OFF_H;     // [32][64]

    const int b = blockIdx.x;
    const int t = threadIdx.x;
    const int w = t >> 5;
    const int lane = t & 31;
    const int lq = lane >> 2;      // 0..7 (quad id / row group)
    const int cq = lane & 3;       // 0..3 (col in quad)
    const int i_sel = w & 3;       // node within i-group
    const int nh = w >> 2;         // column half 0/1

    // ---- load z = concat(x, context) ----
    for (int idx = t; idx < NN * DD; idx += 256) {
        int i = idx / DD, d = idx - i * DD;
        float v = (d < NC) ? x[(b * NN + i) * NC + d]
                           : ctx[(b * NN + i) * CDIM + (d - NC)];
        zsh[i * ZROW + d] = v;
    }
    __syncthreads();

    for (int l = 0; l < NL; ++l) {
        const float* eW1l = eW1 + l * 2 * DD * HDIM;
        const float* eb1l = eb1 + l * HDIM;
        const float* eW2l = eW2 + l * HDIM * HDIM;
        const float* eb2l = eb2 + l * HDIM;
        const float* gWl  = gW  + l * HDIM;
        const float  gbl  = gb[l];
        const float* lngl = lng + l * DD;
        const float* lnbl = lnb + l * DD;
        const float* nW1l = nW1 + l * (DD + HDIM) * HDIM;
        const float* nb1l = nb1 + l * HDIM;
        const float* nW2l = nW2 + l * HDIM * DD;
        const float* nb2l = nb2 + l * DD;

        // ---- stage weights (W2 pre-rounded to tf32) ----
        for (int idx = t; idx < HDIM * HDIM; idx += 256) {
            int k = idx >> 6, n = idx & 63;
            w2sh[k * WROW + n] = __uint_as_float(tf32_rna(eW2l[idx]));
        }
        for (int idx = t; idx < 2 * DD * HDIM; idx += 256) ew1sh[idx] = eW1l[idx];
        __syncthreads();

        // ---- pi / pj projections, row-major [32][76] ----
        for (int idx = t; idx < 32 * HDIM; idx += 256) {
            int i = idx >> 6, k = idx & 63;
            float aI = 0.f, aJ = 0.f;
            if (i < NN) {
                #pragma unroll
                for (int d = 0; d < DD; ++d) {
                    float zv = zsh[i * ZROW + d];
                    aI += zv * ew1sh[d * HDIM + k];
                    aJ += zv * ew1sh[(DD + d) * HDIM + k];
                }
                aI += eb1l[k];
            }
            piR[i * PROW + k] = aI;
            pjR[i * PROW + k] = aJ;
        }

        // ---- layernorm (cheap, overlap here) ----
        if (t < NN) {
            float mu = 0.f, sq = 0.f;
            #pragma unroll
            for (int d = 0; d < DD; ++d) {
                float v = zsh[t * ZROW + d];
                mu += v; sq += v * v;
            }
            mu *= (1.0f / DD);
            float var = sq * (1.0f / DD) - mu * mu;
            float rs = rsqrtf(var + 1e-5f);
            #pragma unroll
            for (int d = 0; d < DD; ++d)
                znsh[t * ZROW + d] = (zsh[t * ZROW + d] - mu) * rs * lngl[d] + lnbl[d];
        }
        __syncthreads();

        // ---- per-thread epilogue constants (8 cols each) ----
        float eb2v[8], gwv[8];
        #pragma unroll
        for (int nf = 0; nf < 4; ++nf) {
            int c = nh * 32 + nf * 8 + cq * 2;
            float2 e2 = *(const float2*)(eb2l + c);
            float2 g2 = *(const float2*)(gWl + c);
            eb2v[nf * 2] = e2.x; eb2v[nf * 2 + 1] = e2.y;
            gwv[nf * 2]  = g2.x; gwv[nf * 2 + 1]  = g2.y;
        }

        // ---- 8 tiles: nodes ig*4..ig*4+3, each warp: 32 jj x 32 cols, K=64 ----
        for (int ig = 0; ig < 8; ++ig) {
            const int node = ig * 4 + i_sel;           // < 32 always
            const float* pib = piR + node * PROW;

            float acc[2][4][4];
            #pragma unroll
            for (int mf = 0; mf < 2; ++mf)
                #pragma unroll
                for (int nf = 0; nf < 4; ++nf)
                    #pragma unroll
                    for (int e = 0; e < 4; ++e) acc[mf][nf][e] = 0.f;

            #pragma unroll
            for (int kk = 0; kk < 8; ++kk) {
                const int k0 = kk * 8 + cq, k1 = k0 + 4;
                const float p0 = pib[k0], p1 = pib[k1];
                uint32_t A[2][4];
                #pragma unroll
                for (int mf = 0; mf < 2; ++mf) {
                    const float* pj0 = pjR + (mf * 16 + lq) * PROW;
                    const float* pj1 = pj0 + 8 * PROW;
                    A[mf][0] = tf32_rna(siluf(p0 + pj0[k0]));
                    A[mf][1] = tf32_rna(siluf(p0 + pj1[k0]));
                    A[mf][2] = tf32_rna(siluf(p1 + pj0[k1]));
                    A[mf][3] = tf32_rna(siluf(p1 + pj1[k1]));
                }
                #pragma unroll
                for (int nf = 0; nf < 4; ++nf) {
                    const int col = nh * 32 + nf * 8 + lq;
                    uint32_t b0 = __float_as_uint(w2sh[(kk * 8 + cq) * WROW + col]);
                    uint32_t b1 = __float_as_uint(w2sh[(kk * 8 + cq + 4) * WROW + col]);
                    mma_tf32(acc[0][nf], A[0], b0, b1);
                    mma_tf32(acc[1][nf], A[1], b0, b1);
                }
            }

            // ---- epilogue: silu + bias, gate partials ----
            float gpart[4] = {0.f, 0.f, 0.f, 0.f};
            #pragma unroll
            for (int mf = 0; mf < 2; ++mf)
                #pragma unroll
                for (int nf = 0; nf < 4; ++nf)
                    #pragma unroll
                    for (int e = 0; e < 4; ++e) {
                        float vv = siluf(acc[mf][nf][e] + eb2v[nf * 2 + (e & 1)]);
                        acc[mf][nf][e] = vv;               // reuse acc as m2
                        gpart[mf * 2 + (e >> 1)] += vv * gwv[nf * 2 + (e & 1)];
                    }
            #pragma unroll
            for (int m = 0; m < 4; ++m) {
                gpart[m] += __shfl_xor_sync(0xffffffffu, gpart[m], 1);
                gpart[m] += __shfl_xor_sync(0xffffffffu, gpart[m], 2);
            }
            float* gbw = gbuf + (ig & 1) * 256 + nh * 128 + i_sel * 32;
            if (cq == 0) {
                #pragma unroll
                for (int m = 0; m < 4; ++m) gbw[lq + 8 * m] = gpart[m];
            }
            __syncthreads();

            // ---- gates + masked aggregate over jj ----
            const float* gbr = gbuf + (ig & 1) * 256 + i_sel * 32;
            float g[4];
            #pragma unroll
            for (int m = 0; m < 4; ++m) {
                int r = lq + 8 * m;
                float gt = gbr[r] + gbr[128 + r] + gbl;
                g[m] = (r < NN) ? sigm(gt) : 0.f;
            }
            float s8[8];
            #pragma unroll
            for (int j = 0; j < 8; ++j) s8[j] = 0.f;
            #pragma unroll
            for (int mf = 0; mf < 2; ++mf)
                #pragma unroll
                for (int nf = 0; nf < 4; ++nf)
                    #pragma unroll
                    for (int e = 0; e < 4; ++e)
                        s8[nf * 2 + (e & 1)] += acc[mf][nf][e] * g[mf * 2 + (e >> 1)];
            #pragma unroll
            for (int j = 0; j < 8; ++j) {
                s8[j] += __shfl_xor_sync(0xffffffffu, s8[j], 4);
                s8[j] += __shfl_xor_sync(0xffffffffu, s8[j], 8);
                s8[j] += __shfl_xor_sync(0xffffffffu, s8[j], 16);
            }
            if (lq == 0 && node < NN) {
                float* mg = magg + node * HDIM + nh * 32;
                #pragma unroll
                for (int nf = 0; nf < 4; ++nf)
                    *(float2*)(mg + nf * 8 + cq * 2) =
                        make_float2(s8[nf * 2], s8[nf * 2 + 1]);
            }
        }
        __syncthreads();

        // ---- node MLP layer 1 ----
        for (int idx = t; idx < NN * HDIM; idx += 256) {
            int i = idx >> 6, m = idx & 63;
            float a = nb1l[m];
            #pragma unroll
            for (int d = 0; d < DD; ++d)
                a += znsh[i * ZROW + d] * nW1l[d * HDIM + m];
            const float* mg = magg + i * HDIM;
            #pragma unroll 8
            for (int d2 = 0; d2 < HDIM; ++d2)
                a += mg[d2] * nW1l[(DD + d2) * HDIM + m];
            hbuf[idx] = siluf(a);
        }
        __syncthreads();

        // ---- node MLP layer 2 + residual ----
        for (int idx = t; idx < NN * DD; idx += 256) {
            int i = idx / DD, d = idx - i * DD;
            float a = nb2l[d];
            #pragma unroll 8
            for (int m2 = 0; m2 < HDIM; ++m2)
                a += hbuf[i * HDIM + m2] * nW2l[m2 * DD + d];
            zsh[i * ZROW + d] += a;
        }
        __syncthreads();
    }

    // ---- mean pool ----
    if (t < DD) {
        float s = 0.f;
        #pragma unroll
        for (int i = 0; i < NN; ++i) s += zsh[i * ZROW + t];
        znsh[t] = s * (1.0f / NN);
    }
    __syncthreads();

    // ---- head MLP ----
    if (t < HDIM) {
        float a = hb1[t];
        #pragma unroll
        for (int d = 0; d < DD; ++d) a += znsh[d] * hW1[d * HDIM + t];
        hbuf[t] = fmaxf(a, 0.f);
    }
    __syncthreads();

    float* ob = out + (size_t)b * (NN * OUTROW);
    for (int idx = t; idx < NN * OUTROW; idx += 256) {
        float v = 0.f;
        if (idx < NOUT) {
            v = hb2[idx];
            #pragma unroll
            for (int m2 = 0; m2 < HDIM; ++m2)
                v += hbuf[m2] * hW2[m2 * NOUT + idx];
        }
        ob[idx] = v;
    }
}

extern "C" void kernel_launch(void* const* d_in, const int* in_sizes, int n_in,
                              void* d_out, int out_size) {
    (void)in_sizes; (void)n_in; (void)out_size;
    const float* x    = (const float*)d_in[0];
    const float* ctx  = (const float*)d_in[1];
    const float* eW1  = (const float*)d_in[2];
    const float* eb1  = (const float*)d_in[3];
    const float* eW2  = (const float*)d_in[4];
    const float* eb2  = (const float*)d_in[5];
    const float* gW   = (const float*)d_in[6];
    const float* gb   = (const float*)d_in[7];
    const float* lng  = (const float*)d_in[8];
    const float* lnb  = (const float*)d_in[9];
    const float* nW1  = (const float*)d_in[10];
    const float* nb1  = (const float*)d_in[11];
    const float* nW2  = (const float*)d_in[12];
    const float* nb2  = (const float*)d_in[13];
    const float* hW1  = (const float*)d_in[14];
    const float* hb1  = (const float*)d_in[15];
    const float* hW2  = (const float*)d_in[16];
    const float* hb2  = (const float*)d_in[17];
    float* out = (float*)d_out;

    cudaFuncSetAttribute(gnn_kernel, cudaFuncAttributeMaxDynamicSharedMemorySize,
                         SMEM_FLOATS * sizeof(float));
    gnn_kernel<<<NB, 256, SMEM_FLOATS * sizeof(float)>>>(
        x, ctx, eW1, eb1, eW2, eb2, gW, gb, lng, lnb,
        nW1, nb1, nW2, nb2, hW1, hb1, hW2, hb2, out);
}

// round 3
// speedup vs baseline: 3.6944x; 1.6216x over previous
#include <cuda_runtime.h>
#include <cstdint>
#include <cstddef>

// Problem constants
#define NB   4096
#define NN   29
#define NC   6
#define CDIM 16
#define DD   22
#define HDIM 64
#define NL   2
#define NOUT 24
#define OUTROW 12
#define ZROW 25     // pad for z/zn rows
#define PROW 76     // pad for pi/pj rows
#define W2PW 136    // floats per w2-pair row (68 float2, 68 % 16 == 4 -> conflict-free)
#define CATW 100    // concat buffer row stride (100 % 32 == 4 -> conflict-free frag loads)

// Shared memory layout (float offsets)
#define OFF_Z    0        // 800
#define OFF_ZN   800      // 800
#define OFF_PI   1600     // 32*76 = 2432
#define OFF_PJ   4032     // 2432
#define OFF_W2P  6464     // 32*136 = 4352 (tf32, (k,k+4) pairs)
#define OFF_EW1  10816    // 44*64 = 2816
#define OFF_MAGG 13632    // 2*32*64 = 4096
#define OFF_H    17728    // 32*64 = 2048
#define SMEM_FLOATS 19776 // 79104 bytes
// catsh [32][100] = 3200 floats aliases OFF_PI..(piR+pjR dead after tile loop)

__device__ __forceinline__ float siluf(float v) {          // accurate-ish silu
    float e = __expf(-v);
    return v * __fdividef(1.0f, 1.0f + e);
}
__device__ __forceinline__ float sigm(float v) {
    float e = __expf(-v);
    return __fdividef(1.0f, 1.0f + e);
}
__device__ __forceinline__ float tanhfast(float x) {
    float y;
    asm("tanh.approx.f32 %0, %1;" : "=f"(y) : "f"(x));
    return y;
}
__device__ __forceinline__ float silu_t(float v) {         // silu via HW tanh
    float h = 0.5f * v;
    return fmaf(h, tanhfast(h), h);
}
__device__ __forceinline__ uint32_t tf32_rna(float x) {
    uint32_t u;
    asm("cvt.rna.tf32.f32 %0, %1;" : "=r"(u) : "f"(x));
    return u;
}
__device__ __forceinline__ void mma_tf32(float c[4], uint32_t a0, uint32_t a1,
                                         uint32_t a2, uint32_t a3,
                                         uint32_t b0, uint32_t b1) {
    asm volatile(
        "mma.sync.aligned.m16n8k8.row.col.f32.tf32.tf32.f32 "
        "{%0,%1,%2,%3}, {%4,%5,%6,%7}, {%8,%9}, {%0,%1,%2,%3};\n"
        : "+f"(c[0]), "+f"(c[1]), "+f"(c[2]), "+f"(c[3])
        : "r"(a0), "r"(a1), "r"(a2), "r"(a3), "r"(b0), "r"(b1));
}

extern "C" __global__ void __launch_bounds__(256, 2)
gnn_kernel(const float* __restrict__ x,   const float* __restrict__ ctx,
           const float* __restrict__ eW1, const float* __restrict__ eb1,
           const float* __restrict__ eW2, const float* __restrict__ eb2,
           const float* __restrict__ gW,  const float* __restrict__ gb,
           const float* __restrict__ lng, const float* __restrict__ lnb,
           const float* __restrict__ nW1, const float* __restrict__ nb1,
           const float* __restrict__ nW2, const float* __restrict__ nb2,
           const float* __restrict__ hW1, const float* __restrict__ hb1,
           const float* __restrict__ hW2, const float* __restrict__ hb2,
           float* __restrict__ out)
{
    extern __shared__ float sh[];
    float* zsh   = sh + OFF_Z;
    float* znsh  = sh + OFF_ZN;
    float* piR   = sh + OFF_PI;    // [32][76]
    float* pjR   = sh + OFF_PJ;    // [32][76]
    float* w2P   = sh + OFF_W2P;   // [32 kp][68 float2]
    float* ew1sh = sh + OFF_EW1;   // [44][64]
    float* magg  = sh + OFF_MAGG;  // [2][32][64]
    float* hbuf  = sh + OFF_H;     // [32][64]
    float* catsh = sh + OFF_PI;    // [32][100]  (aliases piR/pjR, used post-GEMM)

    const int b = blockIdx.x;
    const int t = threadIdx.x;
    const int w = t >> 5;
    const int lane = t & 31;
    const int lq = lane >> 2;      // groupID 0..7
    const int cq = lane & 3;       // threadID-in-group 0..3
    const int i_sel = w >> 1;      // node within i-group (0..3)
    const int jh = w & 1;          // jj half (rows jh*16 .. jh*16+15)
    const int r0 = jh * 16 + lq;   // always < NN
    const int r1 = r0 + 8;         // masked when >= NN

    // ---- load z = concat(x, context) ----
    for (int idx = t; idx < NN * DD; idx += 256) {
        int i = idx / DD, d = idx - i * DD;
        float v = (d < NC) ? x[(b * NN + i) * NC + d]
                           : ctx[(b * NN + i) * CDIM + (d - NC)];
        zsh[i * ZROW + d] = v;
    }
    __syncthreads();

    for (int l = 0; l < NL; ++l) {
        const float* eW1l = eW1 + l * 2 * DD * HDIM;
        const float* eb1l = eb1 + l * HDIM;
        const float* eW2l = eW2 + l * HDIM * HDIM;
        const float* eb2l = eb2 + l * HDIM;
        const float* gWl  = gW  + l * HDIM;
        const float  gbl  = gb[l];
        const float* lngl = lng + l * DD;
        const float* lnbl = lnb + l * DD;
        const float* nW1l = nW1 + l * (DD + HDIM) * HDIM;
        const float* nb1l = nb1 + l * HDIM;
        const float* nW2l = nW2 + l * HDIM * DD;
        const float* nb2l = nb2 + l * DD;

        // ---- stage weights: W2 as tf32 (k,k+4) pairs; eW1 plain ----
        for (int idx = t; idx < HDIM * HDIM; idx += 256) {
            int k = idx >> 6, n = idx & 63;
            int kp = ((k >> 3) << 2) | (k & 3);
            int h  = (k >> 2) & 1;
            w2P[kp * W2PW + n * 2 + h] = __uint_as_float(tf32_rna(eW2l[idx]));
        }
        for (int idx = t; idx < 2 * DD * HDIM; idx += 256) ew1sh[idx] = eW1l[idx];
        __syncthreads();

        // ---- pi / pj projections ----
        for (int idx = t; idx < 32 * HDIM; idx += 256) {
            int i = idx >> 6, k = idx & 63;
            float aI = 0.f, aJ = 0.f;
            if (i < NN) {
                #pragma unroll
                for (int d = 0; d < DD; ++d) {
                    float zv = zsh[i * ZROW + d];
                    aI += zv * ew1sh[d * HDIM + k];
                    aJ += zv * ew1sh[(DD + d) * HDIM + k];
                }
                aI += eb1l[k];
            }
            piR[i * PROW + k] = aI;
            pjR[i * PROW + k] = aJ;
        }
        // ---- layernorm ----
        if (t < NN) {
            float mu = 0.f, sq = 0.f;
            #pragma unroll
            for (int d = 0; d < DD; ++d) {
                float v = zsh[t * ZROW + d];
                mu += v; sq += v * v;
            }
            mu *= (1.0f / DD);
            float var = sq * (1.0f / DD) - mu * mu;
            float rs = rsqrtf(var + 1e-5f);
            #pragma unroll
            for (int d = 0; d < DD; ++d)
                znsh[t * ZROW + d] = (zsh[t * ZROW + d] - mu) * rs * lngl[d] + lnbl[d];
        }
        __syncthreads();

        // per-thread epilogue constants: 16 cols each (nf*8 + 2cq, +1)
        float eb2v[16], gwv[16];
        #pragma unroll
        for (int nf = 0; nf < 8; ++nf) {
            int c = nf * 8 + cq * 2;
            float2 e2 = *(const float2*)(eb2l + c);
            float2 g2 = *(const float2*)(gWl + c);
            eb2v[nf * 2] = e2.x; eb2v[nf * 2 + 1] = e2.y;
            gwv[nf * 2]  = g2.x; gwv[nf * 2 + 1]  = g2.y;
        }

        const float* pj0b = pjR + r0 * PROW;
        const float* pj1b = pjR + r1 * PROW;

        // ---- 8 tiles; warp = (node, jj-half), full 64 cols, NO intra-tile syncs ----
        for (int ig = 0; ig < 8; ++ig) {
            const int node = ig * 4 + i_sel;
            const float* pib = piR + node * PROW;

            float acc[8][4];
            #pragma unroll
            for (int nf = 0; nf < 8; ++nf)
                #pragma unroll
                for (int e = 0; e < 4; ++e) acc[nf][e] = 0.f;

            #pragma unroll
            for (int kk = 0; kk < 8; ++kk) {
                const int k0 = kk * 8 + cq, k1 = k0 + 4;
                const float p0 = pib[k0], p1 = pib[k1];
                uint32_t a0 = tf32_rna(silu_t(p0 + pj0b[k0]));
                uint32_t a1 = tf32_rna(silu_t(p0 + pj1b[k0]));
                uint32_t a2 = tf32_rna(silu_t(p1 + pj0b[k1]));
                uint32_t a3 = tf32_rna(silu_t(p1 + pj1b[k1]));
                const float* wbase = w2P + (kk * 4 + cq) * W2PW;
                #pragma unroll
                for (int nf = 0; nf < 8; ++nf) {
                    float2 bv = *(const float2*)(wbase + (nf * 8 + lq) * 2);
                    mma_tf32(acc[nf], a0, a1, a2, a3,
                             __float_as_uint(bv.x), __float_as_uint(bv.y));
                }
            }

            // ---- epilogue: silu+bias, gate (in-warp), masked aggregate ----
            float gp0 = 0.f, gp1 = 0.f;
            #pragma unroll
            for (int nf = 0; nf < 8; ++nf) {
                float v0 = silu_t(acc[nf][0] + eb2v[nf * 2]);
                float v1 = silu_t(acc[nf][1] + eb2v[nf * 2 + 1]);
                float v2 = silu_t(acc[nf][2] + eb2v[nf * 2]);
                float v3 = silu_t(acc[nf][3] + eb2v[nf * 2 + 1]);
                acc[nf][0] = v0; acc[nf][1] = v1; acc[nf][2] = v2; acc[nf][3] = v3;
                gp0 = fmaf(v0, gwv[nf * 2], gp0);
                gp0 = fmaf(v1, gwv[nf * 2 + 1], gp0);
                gp1 = fmaf(v2, gwv[nf * 2], gp1);
                gp1 = fmaf(v3, gwv[nf * 2 + 1], gp1);
            }
            gp0 += __shfl_xor_sync(0xffffffffu, gp0, 1);
            gp0 += __shfl_xor_sync(0xffffffffu, gp0, 2);
            gp1 += __shfl_xor_sync(0xffffffffu, gp1, 1);
            gp1 += __shfl_xor_sync(0xffffffffu, gp1, 2);
            float g0 = sigm(gp0 + gbl);                       // r0 < NN always
            float g1 = (r1 < NN) ? sigm(gp1 + gbl) : 0.f;

            float s16[16];
            #pragma unroll
            for (int nf = 0; nf < 8; ++nf) {
                s16[nf * 2]     = fmaf(acc[nf][0], g0, acc[nf][2] * g1);
                s16[nf * 2 + 1] = fmaf(acc[nf][1], g0, acc[nf][3] * g1);
            }
            #pragma unroll
            for (int j = 0; j < 16; ++j) {
                s16[j] += __shfl_xor_sync(0xffffffffu, s16[j], 4);
                s16[j] += __shfl_xor_sync(0xffffffffu, s16[j], 8);
                s16[j] += __shfl_xor_sync(0xffffffffu, s16[j], 16);
            }
            if (lq == 0) {
                float* mg = magg + jh * 2048 + node * HDIM;
                #pragma unroll
                for (int nf = 0; nf < 8; ++nf)
                    *(float2*)(mg + nf * 8 + 2 * cq) =
                        make_float2(s16[nf * 2], s16[nf * 2 + 1]);
            }
        }
        __syncthreads();

        // ---- build concat buffer: [zn | m_i | 0-pad], rows >= NN zeroed ----
        for (int idx = t; idx < 32 * HDIM; idx += 256) {
            int i = idx >> 6, c = idx & 63;
            float v = (i < NN) ? magg[idx] + magg[2048 + idx] : 0.f;
            catsh[i * CATW + DD + c] = v;
        }
        for (int idx = t; idx < 32 * DD; idx += 256) {
            int i = idx / DD, d = idx - i * DD;
            catsh[i * CATW + d] = (i < NN) ? znsh[i * ZROW + d] : 0.f;
        }
        if (t < 64) catsh[(t >> 1) * CATW + 86 + (t & 1)] = 0.f;
        __syncthreads();

        // ---- node MLP layer 1 via MMA: [32 x 88] @ [86 x 64] (B direct from GMEM) ----
        {
            const int mh  = w & 1;           // row half
            const int nh4 = w >> 1;          // 16-col group (0..3)
            const int row0 = mh * 16 + lq, row1 = row0 + 8;
            float c2[2][4];
            #pragma unroll
            for (int nfi = 0; nfi < 2; ++nfi)
                #pragma unroll
                for (int e = 0; e < 4; ++e) c2[nfi][e] = 0.f;

            #pragma unroll
            for (int kk = 0; kk < 11; ++kk) {
                const int k0 = kk * 8 + cq, k1 = k0 + 4;
                uint32_t a0 = tf32_rna(catsh[row0 * CATW + k0]);
                uint32_t a1 = tf32_rna(catsh[row1 * CATW + k0]);
                uint32_t a2 = tf32_rna(catsh[row0 * CATW + k1]);
                uint32_t a3 = tf32_rna(catsh[row1 * CATW + k1]);
                #pragma unroll
                for (int nfi = 0; nfi < 2; ++nfi) {
                    const int col = (nh4 * 2 + nfi) * 8 + lq;
                    uint32_t b0 = tf32_rna(nW1l[k0 * HDIM + col]);
                    uint32_t b1 = (k1 < DD + HDIM)
                                ? tf32_rna(nW1l[k1 * HDIM + col]) : 0u;
                    mma_tf32(c2[nfi], a0, a1, a2, a3, b0, b1);
                }
            }
            #pragma unroll
            for (int nfi = 0; nfi < 2; ++nfi) {
                const int colb = (nh4 * 2 + nfi) * 8 + 2 * cq;
                float2 nb = *(const float2*)(nb1l + colb);
                *(float2*)(hbuf + row0 * HDIM + colb) =
                    make_float2(siluf(c2[nfi][0] + nb.x), siluf(c2[nfi][1] + nb.y));
                *(float2*)(hbuf + row1 * HDIM + colb) =
                    make_float2(siluf(c2[nfi][2] + nb.x), siluf(c2[nfi][3] + nb.y));
            }
        }
        __syncthreads();

        // ---- node MLP layer 2 + residual (scalar, small) ----
        for (int idx = t; idx < NN * DD; idx += 256) {
            int i = idx / DD, d = idx - i * DD;
            float a = nb2l[d];
            #pragma unroll 8
            for (int m2 = 0; m2 < HDIM; ++m2)
                a += hbuf[i * HDIM + m2] * nW2l[m2 * DD + d];
            zsh[i * ZROW + d] += a;
        }
        __syncthreads();
    }

    // ---- mean pool ----
    if (t < DD) {
        float s = 0.f;
        #pragma unroll
        for (int i = 0; i < NN; ++i) s += zsh[i * ZROW + t];
        znsh[t] = s * (1.0f / NN);
    }
    __syncthreads();

    // ---- head MLP ----
    if (t < HDIM) {
        float a = hb1[t];
        #pragma unroll
        for (int d = 0; d < DD; ++d) a += znsh[d] * hW1[d * HDIM + t];
        hbuf[t] = fmaxf(a, 0.f);
    }
    __syncthreads();

    float* ob = out + (size_t)b * (NN * OUTROW);
    for (int idx = t; idx < NN * OUTROW; idx += 256) {
        float v = 0.f;
        if (idx < NOUT) {
            v = hb2[idx];
            #pragma unroll
            for (int m2 = 0; m2 < HDIM; ++m2)
                v += hbuf[m2] * hW2[m2 * NOUT + idx];
        }
        ob[idx] = v;
    }
}

extern "C" void kernel_launch(void* const* d_in, const int* in_sizes, int n_in,
                              void* d_out, int out_size) {
    (void)in_sizes; (void)n_in; (void)out_size;
    const float* x    = (const float*)d_in[0];
    const float* ctx  = (const float*)d_in[1];
    const float* eW1  = (const float*)d_in[2];
    const float* eb1  = (const float*)d_in[3];
    const float* eW2  = (const float*)d_in[4];
    const float* eb2  = (const float*)d_in[5];
    const float* gW   = (const float*)d_in[6];
    const float* gb   = (const float*)d_in[7];
    const float* lng  = (const float*)d_in[8];
    const float* lnb  = (const float*)d_in[9];
    const float* nW1  = (const float*)d_in[10];
    const float* nb1  = (const float*)d_in[11];
    const float* nW2  = (const float*)d_in[12];
    const float* nb2  = (const float*)d_in[13];
    const float* hW1  = (const float*)d_in[14];
    const float* hb1  = (const float*)d_in[15];
    const float* hW2  = (const float*)d_in[16];
    const float* hb2  = (const float*)d_in[17];
    float* out = (float*)d_out;

    cudaFuncSetAttribute(gnn_kernel, cudaFuncAttributeMaxDynamicSharedMemorySize,
                         SMEM_FLOATS * sizeof(float));
    gnn_kernel<<<NB, 256, SMEM_FLOATS * sizeof(float)>>>(
        x, ctx, eW1, eb1, eW2, eb2, gW, gb, lng, lnb,
        nW1, nb1, nW2, nb2, hW1, hb1, hW2, hb2, out);
}